// round 3
// baseline (speedup 1.0000x reference)
#include <cuda_runtime.h>
#include <cstdint>

constexpr int NB    = 256;   // batch
constexpr int BSTR  = 65;    // padded stride for [comp][feat] buffers
constexpr int BUFSZ = 64 * BSTR;

struct SMLayout {
    float    buf[3][BUFSZ];   // multivector buffers, comp-major: buf[i*BSTR + f]
    float    LW[BUFSZ];       // staged linear weights [m][f] (stride BSTR); reused for mlp_w1
    float    WGP[BUFSZ];      // staged gp_w per layer: [f][widx] (stride BSTR)
    unsigned tab[4096];       // packed Cayley table [i][out_j]
    float    FACT[256];       // per (f, class) normalize factors; reused as Y4 partials
    int      qts[64];
    int      clss[80];        // 4 classes x up to 20 members
    int      ncls[4];
    float    scratch[160];    // points (96) -> ysh(64)+hsh(64)
};

__device__ unsigned g_tab[4096];
__device__ int      g_qt[64];
__device__ int      g_cls[80];
__device__ int      g_ncls[4];
__device__ float    g_lwT[4 * 4 * 64 * 64];   // [layer][class][m][f]
__device__ float    g_loss_scratch[NB];

// ---------------------------------------------------------------------------
// Init: build algebra tables + transpose gp_lin_w for coalesced staging.
// Table entry for (i, j_out): second-operand index k (as k*65), packed
// w-class index (qt_i, qt_jout, qt_k), and the Cayley sign.
// ---------------------------------------------------------------------------
__global__ void ch_init(const float* __restrict__ gp_lin_w)
{
    const int t = threadIdx.x;
    if (blockIdx.x == 0) {
        __shared__ int s_mask[64], s_pos[64], s_qt[64];
        if (t == 0) {
            int idx = 0;
            for (int g = 0; g <= 6; ++g)
                for (int m = 0; m < 64; ++m)
                    if (__popc(m) == g) s_mask[idx++] = m;
            for (int i = 0; i < 64; ++i) s_pos[s_mask[i]] = i;
            int nc[4] = {0, 0, 0, 0};
            for (int i = 0; i < 64; ++i) {
                const int q = __popc(s_mask[i]) & 3;
                s_qt[i] = q;
                g_qt[i] = q;
                g_cls[q * 20 + nc[q]] = i;
                nc[q]++;
            }
            for (int c = 0; c < 4; ++c) g_ncls[c] = nc[c];
        }
        __syncthreads();
        for (int e = t; e < 4096; e += blockDim.x) {
            const int i = e >> 6, j = e & 63;        // j = OUTPUT component index
            const int mi = s_mask[i];
            const int mk = mi ^ s_mask[j];           // mask of second operand
            const int k  = s_pos[mk];                // second-operand index
            int sgn = 0, tt = mi >> 1;
            while (tt) { sgn += __popc(tt & mk); tt >>= 1; }
            const int widx = (s_qt[i] * 4 + s_qt[j]) * 4 + s_qt[k]; // (qti, qt_out, qt_2nd)
            g_tab[e] = (unsigned)(k * BSTR)
                     | ((unsigned)widx << 16)
                     | ((unsigned)(sgn & 1) << 31);
        }
    } else {
        const int base = (blockIdx.x - 1) * 1024;
        #pragma unroll
        for (int r = 0; r < 4; ++r) {
            const int e = base + r * 256 + t;   // [l][c][m][f]
            const int f = e & 63, m = (e >> 6) & 63, c = (e >> 12) & 3, l = e >> 14;
            g_lwT[e] = gp_lin_w[((l * 64 + f) * 64 + m) * 4 + c];
        }
    }
}

// ---------------------------------------------------------------------------
// Main: one block per batch element.
// ---------------------------------------------------------------------------
__global__ void __launch_bounds__(256, 2)
ch_main(const float* __restrict__ points,
        const float* __restrict__ products,
        const float* __restrict__ lin_w,
        const float* __restrict__ lin_b,
        const float* __restrict__ gp_a,
        const float* __restrict__ gp_w,
        const float* __restrict__ mlp_w1,
        const float* __restrict__ mlp_b1,
        const float* __restrict__ mlp_w2,
        const float* __restrict__ mlp_b2,
        float* __restrict__ lossp)
{
    extern __shared__ unsigned char smraw[];
    SMLayout* s = reinterpret_cast<SMLayout*>(smraw);

    const int t = threadIdx.x;
    const int b = blockIdx.x;

    // ---- stage constants ----
    for (int e = t; e < 4096; e += 256) s->tab[e] = g_tab[e];
    if (t < 64) s->qts[t] = g_qt[t];
    if (t < 80) s->clss[t] = g_cls[t];
    if (t < 4)  s->ncls[t] = g_ncls[t];
    if (t < 96) s->scratch[t] = points[b * 96 + t];

    // ---- zero x buffer ----
    {
        float* A0 = s->buf[0];
        for (int e = t; e < BUFSZ; e += 256) A0[e] = 0.f;
    }
    __syncthreads();

    // ---- initial qt_linear (grade-1 inputs only -> class 1 weights; bias on comp 0)
    {
        float* A0 = s->buf[0];
        if (t < 64) A0[t] = lin_b[t];                  // comp 0
        for (int o = t; o < 384; o += 256) {
            const int f = o / 6, d = o % 6;
            float acc = 0.f;
            #pragma unroll
            for (int m = 0; m < 16; ++m)
                acc = fmaf(s->scratch[m * 6 + d], __ldg(&lin_w[(f * 16 + m) * 4 + 1]), acc);
            A0[(1 + d) * BSTR + f] = acc;
        }
    }
    __syncthreads();

    // ---- 4 GP layers ----
    int oa = 0, oc = 2;
    for (int l = 0; l < 4; ++l) {
        float* A = s->buf[oa];
        float* B = s->buf[1];
        float* C = s->buf[oc];

        // qt_linear: B[i][f] = sum_m A[i][m] * gp_lin_w[l,f,m,qt(i)] (class-staged)
        {
            const float* lwTl = g_lwT + l * 4 * 4096;
            const int f64 = t & 63, ig = t >> 6;
            for (int c = 0; c < 4; ++c) {
                __syncthreads();
                const float* src = lwTl + c * 4096;
                for (int e = t; e < 4096; e += 256)
                    s->LW[(e >> 6) * BSTR + (e & 63)] = src[e];   // [m][f]
                __syncthreads();
                const int nc = s->ncls[c];
                const int* cl = s->clss + c * 20;
                for (int idx = ig; idx < nc; idx += 8) {
                    const int i0 = cl[idx];
                    const bool has1 = (idx + 4) < nc;
                    const int i1 = has1 ? cl[idx + 4] : i0;
                    const float* Ar0 = A + i0 * BSTR;
                    const float* Ar1 = A + i1 * BSTR;
                    float a0 = 0.f, a1 = 0.f;
                    #pragma unroll
                    for (int m = 0; m < 64; ++m) {
                        const float w = s->LW[m * BSTR + f64];
                        a0 = fmaf(Ar0[m], w, a0);
                        a1 = fmaf(Ar1[m], w, a1);
                    }
                    B[i0 * BSTR + f64] = a0;
                    if (has1) B[i1 * BSTR + f64] = a1;
                }
            }
        }
        __syncthreads();

        // normalize B per (feature, qt-class)
        {
            const int ff = t & 63, c = t >> 6;
            const int nc = s->ncls[c];
            const int* cl = s->clss + c * 20;
            float sum = 0.f;
            for (int idx = 0; idx < nc; ++idx) {
                const float v = B[cl[idx] * BSTR + ff];
                sum = fmaf(v, v, sum);
            }
            const float nrm = sqrtf(fmaxf(sum, 1e-12f));
            const float av  = gp_a[(l * 64 + ff) * 4 + c];
            const float sig = 1.f / (1.f + expf(-av));
            s->FACT[ff * 4 + c] = 1.f / (fmaf(sig, nrm - 1.f, 1.f) + 1e-6f);
        }
        __syncthreads();
        for (int r = 0; r < 16; ++r) {
            const int e = r * 256 + t;
            const int i = e >> 6, ff = e & 63;
            B[i * BSTR + ff] *= s->FACT[ff * 4 + s->qts[i]];
        }
        // stage gp_w for this layer: WGP[f][widx]
        {
            const float* gw = gp_w + l * 4096;
            for (int e = t; e < 4096; e += 256)
                s->WGP[(e >> 6) * BSTR + (e & 63)] = gw[e];
        }
        __syncthreads();

        // geometric product: C[j][f] = sum_i sign * w[f,qti,qtj,qtk] * A[i][f] * B[k][f]
        {
            const int ff = t >> 2, jg = t & 3;
            const float* Af = A + ff;
            const float* Bf = B + ff;
            const float* Wf = s->WGP + ff * BSTR;
            const uint4* trow = reinterpret_cast<const uint4*>(s->tab) + jg * 4;
            float acc[16];
            #pragma unroll
            for (int q = 0; q < 16; ++q) acc[q] = 0.f;
            for (int i = 0; i < 64; ++i) {
                const float xi = Af[i * BSTR];
                const uint4 v0 = trow[i * 16 + 0];
                const uint4 v1 = trow[i * 16 + 1];
                const uint4 v2 = trow[i * 16 + 2];
                const uint4 v3 = trow[i * 16 + 3];
                const unsigned es[16] = { v0.x, v0.y, v0.z, v0.w,
                                          v1.x, v1.y, v1.z, v1.w,
                                          v2.x, v2.y, v2.z, v2.w,
                                          v3.x, v3.y, v3.z, v3.w };
                #pragma unroll
                for (int q = 0; q < 16; ++q) {
                    const unsigned e = es[q];
                    float p = xi * Bf[e & 0x1FFFu];
                    p = __int_as_float(__float_as_int(p) ^ (int)(e & 0x80000000u));
                    acc[q] = fmaf(Wf[(e >> 16) & 63u], p, acc[q]);
                }
            }
            #pragma unroll
            for (int q = 0; q < 16; ++q)
                C[(jg * 16 + q) * BSTR + ff] = acc[q];
        }
        __syncthreads();

        const int tmp = oa; oa = oc; oc = tmp;   // new x = C
    }

    // ---- final: y = ||x||, h = silu(y@W1^T + b1), pred = h@w2 + b2, loss ----
    {
        float* X  = s->buf[oa];
        float* Y4 = s->FACT;   // reuse: 4 partials x 64 features
        {
            const int ff = t & 63, part = t >> 6;
            float sum = 0.f;
            #pragma unroll
            for (int r = 0; r < 16; ++r) {
                const float v = X[(part * 16 + r) * BSTR + ff];
                sum = fmaf(v, v, sum);
            }
            Y4[part * 64 + ff] = sum;
        }
        __syncthreads();
        float* ysh = s->scratch;        // 64
        float* hsh = s->scratch + 64;   // 64
        if (t < 64) ysh[t] = sqrtf(Y4[t] + Y4[64 + t] + Y4[128 + t] + Y4[192 + t]);
        // stage mlp_w1 as [f][n] (stride BSTR)
        for (int e = t; e < 4096; e += 256) {
            const int n = e >> 6, f = e & 63;
            s->LW[f * BSTR + n] = mlp_w1[e];
        }
        __syncthreads();
        if (t < 64) {
            float a = mlp_b1[t];
            #pragma unroll
            for (int f = 0; f < 64; ++f)
                a = fmaf(ysh[f], s->LW[f * BSTR + t], a);
            const float sig = 1.f / (1.f + expf(-a));
            hsh[t] = a * sig * __ldg(&mlp_w2[t]);   // fold in w2
        }
        __syncthreads();
        if (t == 0) {
            float p = mlp_b2[0];
            for (int n = 0; n < 64; ++n) p += hsh[n];
            const float d = p - products[b];
            lossp[b] = d * d;
        }
    }
}

// ---------------------------------------------------------------------------
// Mean reduce (deterministic tree)
// ---------------------------------------------------------------------------
__global__ void ch_reduce(const float* __restrict__ lossp, float* __restrict__ out)
{
    __shared__ float sred[NB];
    const int t = threadIdx.x;
    sred[t] = lossp[t];
    __syncthreads();
    for (int sft = NB / 2; sft > 0; sft >>= 1) {
        if (t < sft) sred[t] += sred[t + sft];
        __syncthreads();
    }
    if (t == 0) out[0] = sred[0] * (1.0f / (float)NB);
}

extern "C" void kernel_launch(void* const* d_in, const int* in_sizes, int n_in,
                              void* d_out, int out_size)
{
    const float* points   = (const float*)d_in[0];
    const float* products = (const float*)d_in[1];
    const float* lin_w    = (const float*)d_in[2];
    const float* lin_b    = (const float*)d_in[3];
    const float* gp_lin_w = (const float*)d_in[4];
    const float* gp_a     = (const float*)d_in[5];
    const float* gp_w     = (const float*)d_in[6];
    const float* mlp_w1   = (const float*)d_in[7];
    const float* mlp_b1   = (const float*)d_in[8];
    const float* mlp_w2   = (const float*)d_in[9];
    const float* mlp_b2   = (const float*)d_in[10];
    float* out = (float*)d_out;

    static bool attr_set = false;
    if (!attr_set) {
        cudaFuncSetAttribute(ch_main, cudaFuncAttributeMaxDynamicSharedMemorySize,
                             (int)sizeof(SMLayout));
        attr_set = true;
    }

    ch_init<<<65, 256>>>(gp_lin_w);

    float* lossp;
    bool write_mean = true;
    if (out_size >= NB + 1) {
        lossp = out + 1;                 // layout: [mean, loss[256]]
    } else if (out_size == NB) {
        lossp = out;                     // loss only, no mean slot
        write_mean = false;
    } else {
        void* p = nullptr;
        cudaGetSymbolAddress(&p, g_loss_scratch);
        lossp = (float*)p;               // mean only
    }

    ch_main<<<NB, 256, sizeof(SMLayout)>>>(points, products, lin_w, lin_b,
                                           gp_a, gp_w, mlp_w1, mlp_b1,
                                           mlp_w2, mlp_b2, lossp);
    if (write_mean)
        ch_reduce<<<1, NB>>>(lossp, out);
}

// round 4
// speedup vs baseline: 3.0858x; 3.0858x over previous
#include <cuda_runtime.h>

constexpr int NB = 256;

constexpr int cpopc(int x){int c=0;while(x){c+=x&1;x>>=1;}return c;}

struct Alg {
    int qt[64];
    short kk[64][64];     // k(i,j)
    short sx[64][64];     // widx + 64*sign
    int   cls[4][20];
    int   ncl[4];
};
constexpr Alg build_alg(){
    Alg a{};
    int mask[64]={}, pos[64]={};
    int idx=0;
    for(int g=0;g<=6;++g) for(int m=0;m<64;++m) if(cpopc(m)==g){mask[idx]=m;idx++;}
    for(int i=0;i<64;++i) pos[mask[i]]=i;
    for(int i=0;i<64;++i){
        a.qt[i]=cpopc(mask[i])&3;
        a.cls[a.qt[i]][a.ncl[a.qt[i]]]=i;
        a.ncl[a.qt[i]]++;
    }
    for(int i=0;i<64;++i) for(int j=0;j<64;++j){
        const int mk=mask[i]^mask[j];
        const int k=pos[mk];
        int s=0,t=mask[i]>>1;
        while(t){s+=cpopc(t&mk);t>>=1;}
        a.kk[i][j]=(short)k;
        a.sx[i][j]=(short)(((a.qt[i]*4+a.qt[j])*4+a.qt[k]) + ((s&1)?64:0));
    }
    return a;
}
__device__ constexpr Alg ALG = build_alg();

__device__ float g_lwT[4*4*64*64];   // [l][c][m][f]
__device__ float g_lin1T[1024];      // [m][f]
__device__ float g_loss_scratch[NB];

__global__ void ch_init(const float* __restrict__ gp_lin_w,
                        const float* __restrict__ lin_w)
{
    const int t = threadIdx.x;
    if (blockIdx.x < 64) {
        #pragma unroll
        for (int r=0;r<4;++r){
            const int o = blockIdx.x*1024 + r*256 + t;      // [l][c][m][f]
            const int f=o&63, m=(o>>6)&63, c=(o>>12)&3, l=o>>14;
            g_lwT[o] = gp_lin_w[((l*64+f)*64+m)*4 + c];
        }
    } else {
        #pragma unroll
        for (int r=0;r<4;++r){
            const int e=r*256+t, m=e>>6, f=e&63;
            g_lin1T[e] = lin_w[(f*16+m)*4 + 1];
        }
    }
}

struct SM {
    float A[4096];      // x [i*64+f]
    float Bv[4224];     // xr [i*64+f]; reused for mlp_w1 [f*65+n]
    float W[4160];      // gp_w [f*65+widx]
    float F[256];       // factors / partial sums [c*64+f]
    float y[64], h[64], pts[96];
};

template<int JQ>
__device__ __forceinline__ void sec_lin(const float* __restrict__ Ash,
                                        float* __restrict__ Bvf,
                                        const float* __restrict__ lwf)
{
    float LW[64];
    #pragma unroll
    for (int i=JQ*16; i<JQ*16+16; ++i) {
        if (i==JQ*16 || ALG.qt[i]!=ALG.qt[i-1]) {
            const float* p = lwf + ALG.qt[i]*4096;
            #pragma unroll
            for (int m=0;m<64;++m) LW[m] = p[m*64];
        }
        const float4* Ar = reinterpret_cast<const float4*>(Ash + i*64);
        float acc = 0.f;
        #pragma unroll
        for (int mq=0;mq<16;++mq){
            const float4 a = Ar[mq];
            acc = fmaf(a.x, LW[4*mq+0], acc);
            acc = fmaf(a.y, LW[4*mq+1], acc);
            acc = fmaf(a.z, LW[4*mq+2], acc);
            acc = fmaf(a.w, LW[4*mq+3], acc);
        }
        Bvf[i*64] = acc;
    }
}

template<int C>
__device__ __forceinline__ void sec_fact(const float* __restrict__ Bvf,
                                         float* __restrict__ Ff,
                                         const float* __restrict__ gp_a,
                                         int l, int f)
{
    float s = 0.f;
    #pragma unroll
    for (int u=0; u<ALG.ncl[C]; ++u) {
        const float v = Bvf[ALG.cls[C][u]*64];
        s = fmaf(v, v, s);
    }
    const float nrm = sqrtf(fmaxf(s, 1e-12f));
    const float av  = gp_a[(l*64+f)*4 + C];
    const float sig = 1.f/(1.f+expf(-av));
    Ff[C*64] = 1.f/(fmaf(sig, nrm-1.f, 1.f) + 1e-6f);
}

template<int JQ>
__device__ __forceinline__ void sec_gp(const float* __restrict__ Af,
                                       const float* __restrict__ Bvf,
                                       const float* __restrict__ Wf,
                                       const float* __restrict__ Ff,
                                       float (&acc)[16])
{
    float fc[4];
    #pragma unroll
    for (int c=0;c<4;++c) fc[c] = Ff[c*64];
    float B[64];
    #pragma unroll
    for (int k=0;k<64;++k) B[k] = Bvf[k*64] * fc[ALG.qt[k]];
    #pragma unroll
    for (int q=0;q<16;++q) acc[q]=0.f;
    #pragma unroll
    for (int i=0;i<64;++i) {
        const float xi = Af[i*64];
        #pragma unroll
        for (int q=0;q<16;++q) {
            const int j = JQ*16+q;
            const float p = xi * B[ALG.kk[i][j]];
            const int sxv = ALG.sx[i][j];
            acc[q] = (sxv & 64) ? fmaf(Wf[sxv & 63], -p, acc[q])
                                : fmaf(Wf[sxv & 63],  p, acc[q]);
        }
    }
}

__global__ void __launch_bounds__(256, 2)
ch_main(const float* __restrict__ points,
        const float* __restrict__ products,
        const float* __restrict__ lin_b,
        const float* __restrict__ gp_a,
        const float* __restrict__ gp_w,
        const float* __restrict__ mlp_w1,
        const float* __restrict__ mlp_b1,
        const float* __restrict__ mlp_w2,
        const float* __restrict__ mlp_b2,
        float* __restrict__ lossp)
{
    extern __shared__ unsigned char smraw[];
    SM* s = reinterpret_cast<SM*>(smraw);

    const int t  = threadIdx.x;
    const int b  = blockIdx.x;
    const int f  = t & 63;
    const int jq = t >> 6;

    if (t < 96) s->pts[t] = points[b*96 + t];
    for (int e = 448 + t; e < 4096; e += 256) s->A[e] = 0.f;
    if (t < 64) s->A[t] = lin_b[t];
    __syncthreads();

    for (int d = jq; d < 6; d += 4) {
        float acc = 0.f;
        #pragma unroll
        for (int m=0;m<16;++m)
            acc = fmaf(s->pts[m*6+d], g_lin1T[m*64+f], acc);
        s->A[(1+d)*64 + f] = acc;
    }
    __syncthreads();

    float acc[16];
    for (int l = 0; l < 4; ++l) {
        // stage gp_w: W[f*65+w]
        {
            const float* gw = gp_w + l*4096;
            #pragma unroll
            for (int r=0;r<16;++r) {
                const int e = r*256+t, ff=e>>6, w=e&63;
                s->W[ff*65+w] = gw[e];
            }
        }
        switch (jq) {
            case 0:  sec_lin<0>(s->A, s->Bv+f, g_lwT + l*16384 + f); break;
            case 1:  sec_lin<1>(s->A, s->Bv+f, g_lwT + l*16384 + f); break;
            case 2:  sec_lin<2>(s->A, s->Bv+f, g_lwT + l*16384 + f); break;
            default: sec_lin<3>(s->A, s->Bv+f, g_lwT + l*16384 + f); break;
        }
        __syncthreads();
        switch (jq) {
            case 0:  sec_fact<0>(s->Bv+f, s->F+f, gp_a, l, f); break;
            case 1:  sec_fact<1>(s->Bv+f, s->F+f, gp_a, l, f); break;
            case 2:  sec_fact<2>(s->Bv+f, s->F+f, gp_a, l, f); break;
            default: sec_fact<3>(s->Bv+f, s->F+f, gp_a, l, f); break;
        }
        __syncthreads();
        switch (jq) {
            case 0:  sec_gp<0>(s->A+f, s->Bv+f, s->W+f*65, s->F+f, acc); break;
            case 1:  sec_gp<1>(s->A+f, s->Bv+f, s->W+f*65, s->F+f, acc); break;
            case 2:  sec_gp<2>(s->A+f, s->Bv+f, s->W+f*65, s->F+f, acc); break;
            default: sec_gp<3>(s->A+f, s->Bv+f, s->W+f*65, s->F+f, acc); break;
        }
        __syncthreads();
        #pragma unroll
        for (int q=0;q<16;++q) s->A[(jq*16+q)*64+f] = acc[q];
        __syncthreads();
    }

    // epilogue: norms, MLP, loss
    {
        float sum = 0.f;
        #pragma unroll
        for (int r=0;r<16;++r) {
            const float v = s->A[(jq*16+r)*64+f];
            sum = fmaf(v, v, sum);
        }
        s->F[jq*64+f] = sum;
    }
    // stage mlp_w1 -> Bv[f*65+n]
    #pragma unroll
    for (int r=0;r<16;++r) {
        const int e = r*256+t, n=e>>6, ff=e&63;
        s->Bv[ff*65+n] = mlp_w1[e];
    }
    __syncthreads();
    if (t < 64) s->y[t] = sqrtf(s->F[t] + s->F[64+t] + s->F[128+t] + s->F[192+t]);
    __syncthreads();
    if (t < 64) {
        float a = mlp_b1[t];
        #pragma unroll
        for (int ff=0;ff<64;++ff)
            a = fmaf(s->y[ff], s->Bv[ff*65+t], a);
        const float sig = 1.f/(1.f+expf(-a));
        s->h[t] = a * sig * mlp_w2[t];
    }
    __syncthreads();
    if (t == 0) {
        float p = mlp_b2[0];
        for (int n=0;n<64;++n) p += s->h[n];
        const float d = p - products[b];
        lossp[b] = d*d;
    }
}

__global__ void ch_reduce(const float* __restrict__ lossp, float* __restrict__ out)
{
    __shared__ float sred[NB];
    const int t = threadIdx.x;
    sred[t] = lossp[t];
    __syncthreads();
    for (int sft = NB/2; sft > 0; sft >>= 1) {
        if (t < sft) sred[t] += sred[t+sft];
        __syncthreads();
    }
    if (t == 0) out[0] = sred[0] * (1.0f/(float)NB);
}

extern "C" void kernel_launch(void* const* d_in, const int* in_sizes, int n_in,
                              void* d_out, int out_size)
{
    const float* points   = (const float*)d_in[0];
    const float* products = (const float*)d_in[1];
    const float* lin_w    = (const float*)d_in[2];
    const float* lin_b    = (const float*)d_in[3];
    const float* gp_lin_w = (const float*)d_in[4];
    const float* gp_a     = (const float*)d_in[5];
    const float* gp_w     = (const float*)d_in[6];
    const float* mlp_w1   = (const float*)d_in[7];
    const float* mlp_b1   = (const float*)d_in[8];
    const float* mlp_w2   = (const float*)d_in[9];
    const float* mlp_b2   = (const float*)d_in[10];
    float* out = (float*)d_out;

    static bool attr_set = false;
    if (!attr_set) {
        cudaFuncSetAttribute(ch_main, cudaFuncAttributeMaxDynamicSharedMemorySize,
                             (int)sizeof(SM));
        attr_set = true;
    }

    ch_init<<<65, 256>>>(gp_lin_w, lin_w);

    float* lossp;
    bool write_mean = true;
    if (out_size >= NB + 1) {
        lossp = out + 1;
    } else if (out_size == NB) {
        lossp = out; write_mean = false;
    } else {
        void* p = nullptr;
        cudaGetSymbolAddress(&p, g_loss_scratch);
        lossp = (float*)p;
    }

    ch_main<<<NB, 256, sizeof(SM)>>>(points, products, lin_b, gp_a, gp_w,
                                     mlp_w1, mlp_b1, mlp_w2, mlp_b2, lossp);
    if (write_mean)
        ch_reduce<<<1, NB>>>(lossp, out);
}

// round 7
// speedup vs baseline: 3.1465x; 1.0197x over previous
#include <cuda_runtime.h>

constexpr int NB = 256;

constexpr int cpopc(int x){int c=0;while(x){c+=x&1;x>>=1;}return c;}

struct Alg {
    int qt[64];
    short kk[64][64];     // k(i,j)
    short sx[64][64];     // widx + 64*sign
    int   cls[4][20];
    int   ncl[4];
    int   perm[4][16];    // row assignment per jq-group (class-grouped)
};
constexpr Alg build_alg(){
    Alg a{};
    int mask[64]={}, pos[64]={};
    int idx=0;
    for(int g=0;g<=6;++g) for(int m=0;m<64;++m) if(cpopc(m)==g){mask[idx]=m;idx++;}
    for(int i=0;i<64;++i) pos[mask[i]]=i;
    for(int i=0;i<64;++i){
        a.qt[i]=cpopc(mask[i])&3;
        a.cls[a.qt[i]][a.ncl[a.qt[i]]]=i;
        a.ncl[a.qt[i]]++;
    }
    for(int i=0;i<64;++i) for(int j=0;j<64;++j){
        const int mk=mask[i]^mask[j];
        const int k=pos[mk];
        int s=0,t=mask[i]>>1;
        while(t){s+=cpopc(t&mk);t>>=1;}
        a.kk[i][j]=(short)k;
        a.sx[i][j]=(short)(((a.qt[i]*4+a.qt[j])*4+a.qt[k]) + ((s&1)?64:0));
    }
    // class-grouped permutation: ncl = {16,12,16,20}
    for(int q=0;q<16;++q) a.perm[0][q]=a.cls[0][q];           // 16 x c0
    for(int q=0;q<12;++q) a.perm[1][q]=a.cls[1][q];           // 12 x c1
    for(int q=0;q<4; ++q) a.perm[1][12+q]=a.cls[3][q];        //  4 x c3
    for(int q=0;q<16;++q) a.perm[2][q]=a.cls[2][q];           // 16 x c2
    for(int q=0;q<16;++q) a.perm[3][q]=a.cls[3][4+q];         // 16 x c3
    return a;
}
__device__ constexpr Alg ALG = build_alg();

__device__ float g_lwT[4*4*64*64];   // [l][c][m][f]
__device__ float g_lin1T[1024];      // [m][f]
__device__ float g_loss_scratch[NB];

// Coalesced init: one float4 (c=0..3) per (l,f,m) tuple.
__global__ void ch_init(const float* __restrict__ gp_lin_w,
                        const float* __restrict__ lin_w)
{
    const int t = threadIdx.x;
    if (blockIdx.x < 64) {
        const int s = blockIdx.x*256 + t;          // (l,f,m), m fastest
        const int m = s & 63, f = (s>>6) & 63, l = s>>12;
        const float4 v = reinterpret_cast<const float4*>(gp_lin_w)[s];
        float* dst = g_lwT + l*16384 + m*64 + f;
        dst[0]       = v.x;
        dst[4096]    = v.y;
        dst[8192]    = v.z;
        dst[12288]   = v.w;
    } else {
        #pragma unroll
        for (int r=0;r<4;++r){
            const int e=r*256+t, m=e>>6, f=e&63;
            g_lin1T[e] = lin_w[(f*16+m)*4 + 1];
        }
    }
}

struct SM {
    float A[4096];      // x [i*64+f]
    float Bv[4224];     // xr [i*64+f]; reused for mlp_w1 [f*65+n]
    float W[4160];      // gp_w [f*65+widx]
    float F[256];       // factors / partials [c*64+f]
    float y[64], h[64], pts[96];
};

template<int JQ>
__device__ __forceinline__ void sec_lin(const float* __restrict__ Ash,
                                        float* __restrict__ Bvf,
                                        const float* __restrict__ lwf)
{
    float LW[64];
    #pragma unroll
    for (int q=0;q<16;++q) {
        constexpr auto P = ALG.perm[JQ];
        const int i = P[q];
        if (q==0 || ALG.qt[P[q]]!=ALG.qt[P[q-1]]) {
            const float* p = lwf + ALG.qt[i]*4096;
            #pragma unroll
            for (int m=0;m<64;++m) LW[m] = p[m*64];
        }
        const float4* Ar = reinterpret_cast<const float4*>(Ash + i*64);
        float acc = 0.f;
        #pragma unroll
        for (int mq=0;mq<16;++mq){
            const float4 a = Ar[mq];
            acc = fmaf(a.x, LW[4*mq+0], acc);
            acc = fmaf(a.y, LW[4*mq+1], acc);
            acc = fmaf(a.z, LW[4*mq+2], acc);
            acc = fmaf(a.w, LW[4*mq+3], acc);
        }
        Bvf[i*64] = acc;
    }
}

template<int C>
__device__ __forceinline__ void sec_fact(const float* __restrict__ Bvf,
                                         float* __restrict__ Ff,
                                         const float* __restrict__ gp_a,
                                         int l, int f)
{
    float s = 0.f;
    #pragma unroll
    for (int u=0; u<ALG.ncl[C]; ++u) {
        const float v = Bvf[ALG.cls[C][u]*64];
        s = fmaf(v, v, s);
    }
    const float nrm = sqrtf(fmaxf(s, 1e-12f));
    const float av  = gp_a[(l*64+f)*4 + C];
    const float sig = 1.f/(1.f+expf(-av));
    Ff[C*64] = 1.f/(fmaf(sig, nrm-1.f, 1.f) + 1e-6f);
}

template<int JQ>
__device__ __forceinline__ void sec_gp(const float* __restrict__ Af,
                                       const float* __restrict__ Bvf,
                                       const float* __restrict__ Wf,
                                       const float* __restrict__ Ff,
                                       float (&acc)[16])
{
    float fc[4];
    #pragma unroll
    for (int c=0;c<4;++c) fc[c] = Ff[c*64];
    float B[64];
    #pragma unroll
    for (int k=0;k<64;++k) B[k] = Bvf[k*64] * fc[ALG.qt[k]];
    #pragma unroll
    for (int q=0;q<16;++q) acc[q]=0.f;
    #pragma unroll
    for (int i=0;i<64;++i) {
        const float xi = Af[i*64];
        #pragma unroll
        for (int q=0;q<16;++q) {
            const int j = ALG.perm[JQ][q];
            const float p = xi * B[ALG.kk[i][j]];
            const int sxv = ALG.sx[i][j];
            acc[q] = (sxv & 64) ? fmaf(Wf[sxv & 63], -p, acc[q])
                                : fmaf(Wf[sxv & 63],  p, acc[q]);
        }
    }
}

template<int JQ>
__device__ __forceinline__ void sec_store(float* __restrict__ Ash, int f,
                                          const float (&acc)[16])
{
    #pragma unroll
    for (int q=0;q<16;++q)
        Ash[ALG.perm[JQ][q]*64 + f] = acc[q];
}

__global__ void __launch_bounds__(256, 2)
ch_main(const float* __restrict__ points,
        const float* __restrict__ products,
        const float* __restrict__ lin_b,
        const float* __restrict__ gp_a,
        const float* __restrict__ gp_w,
        const float* __restrict__ mlp_w1,
        const float* __restrict__ mlp_b1,
        const float* __restrict__ mlp_w2,
        const float* __restrict__ mlp_b2,
        float* __restrict__ lossp)
{
    extern __shared__ unsigned char smraw[];
    SM* s = reinterpret_cast<SM*>(smraw);

    const int t  = threadIdx.x;
    const int b  = blockIdx.x;
    const int f  = t & 63;
    const int jq = t >> 6;

    if (t < 96) s->pts[t] = points[b*96 + t];
    for (int e = 448 + t; e < 4096; e += 256) s->A[e] = 0.f;
    if (t < 64) s->A[t] = lin_b[t];
    __syncthreads();

    for (int d = jq; d < 6; d += 4) {
        float acc = 0.f;
        #pragma unroll
        for (int m=0;m<16;++m)
            acc = fmaf(s->pts[m*6+d], g_lin1T[m*64+f], acc);
        s->A[(1+d)*64 + f] = acc;
    }
    __syncthreads();

    float acc[16];
    for (int l = 0; l < 4; ++l) {
        {   // stage gp_w: W[f*65+w]
            const float* gw = gp_w + l*4096;
            #pragma unroll
            for (int r=0;r<16;++r) {
                const int e = r*256+t, ff=e>>6, w=e&63;
                s->W[ff*65+w] = gw[e];
            }
        }
        switch (jq) {
            case 0:  sec_lin<0>(s->A, s->Bv+f, g_lwT + l*16384 + f); break;
            case 1:  sec_lin<1>(s->A, s->Bv+f, g_lwT + l*16384 + f); break;
            case 2:  sec_lin<2>(s->A, s->Bv+f, g_lwT + l*16384 + f); break;
            default: sec_lin<3>(s->A, s->Bv+f, g_lwT + l*16384 + f); break;
        }
        __syncthreads();
        switch (jq) {
            case 0:  sec_fact<0>(s->Bv+f, s->F+f, gp_a, l, f); break;
            case 1:  sec_fact<1>(s->Bv+f, s->F+f, gp_a, l, f); break;
            case 2:  sec_fact<2>(s->Bv+f, s->F+f, gp_a, l, f); break;
            default: sec_fact<3>(s->Bv+f, s->F+f, gp_a, l, f); break;
        }
        __syncthreads();
        switch (jq) {
            case 0:  sec_gp<0>(s->A+f, s->Bv+f, s->W+f*65, s->F+f, acc); break;
            case 1:  sec_gp<1>(s->A+f, s->Bv+f, s->W+f*65, s->F+f, acc); break;
            case 2:  sec_gp<2>(s->A+f, s->Bv+f, s->W+f*65, s->F+f, acc); break;
            default: sec_gp<3>(s->A+f, s->Bv+f, s->W+f*65, s->F+f, acc); break;
        }
        __syncthreads();
        switch (jq) {
            case 0:  sec_store<0>(s->A, f, acc); break;
            case 1:  sec_store<1>(s->A, f, acc); break;
            case 2:  sec_store<2>(s->A, f, acc); break;
            default: sec_store<3>(s->A, f, acc); break;
        }
        __syncthreads();
    }

    // epilogue: norms, MLP, loss
    {
        float sum = 0.f;
        #pragma unroll
        for (int r=0;r<16;++r) {
            const float v = s->A[(jq*16+r)*64+f];
            sum = fmaf(v, v, sum);
        }
        s->F[jq*64+f] = sum;
    }
    #pragma unroll
    for (int r=0;r<16;++r) {              // stage mlp_w1 -> Bv[f*65+n]
        const int e = r*256+t, n=e>>6, ff=e&63;
        s->Bv[ff*65+n] = mlp_w1[e];
    }
    __syncthreads();
    if (t < 64) s->y[t] = sqrtf(s->F[t] + s->F[64+t] + s->F[128+t] + s->F[192+t]);
    __syncthreads();
    if (t < 64) {
        float a = mlp_b1[t];
        #pragma unroll
        for (int ff=0;ff<64;++ff)
            a = fmaf(s->y[ff], s->Bv[ff*65+t], a);
        const float sig = 1.f/(1.f+expf(-a));
        s->h[t] = a * sig * mlp_w2[t];
    }
    __syncthreads();
    if (t == 0) {
        float p = mlp_b2[0];
        for (int n=0;n<64;++n) p += s->h[n];
        const float d = p - products[b];
        lossp[b] = d*d;
    }
}

__global__ void ch_reduce(const float* __restrict__ lossp, float* __restrict__ out)
{
    __shared__ float sred[NB];
    const int t = threadIdx.x;
    sred[t] = lossp[t];
    __syncthreads();
    for (int sft = NB/2; sft > 0; sft >>= 1) {
        if (t < sft) sred[t] += sred[t+sft];
        __syncthreads();
    }
    if (t == 0) out[0] = sred[0] * (1.0f/(float)NB);
}

extern "C" void kernel_launch(void* const* d_in, const int* in_sizes, int n_in,
                              void* d_out, int out_size)
{
    const float* points   = (const float*)d_in[0];
    const float* products = (const float*)d_in[1];
    const float* lin_w    = (const float*)d_in[2];
    const float* lin_b    = (const float*)d_in[3];
    const float* gp_lin_w = (const float*)d_in[4];
    const float* gp_a     = (const float*)d_in[5];
    const float* gp_w     = (const float*)d_in[6];
    const float* mlp_w1   = (const float*)d_in[7];
    const float* mlp_b1   = (const float*)d_in[8];
    const float* mlp_w2   = (const float*)d_in[9];
    const float* mlp_b2   = (const float*)d_in[10];
    float* out = (float*)d_out;

    static bool attr_set = false;
    if (!attr_set) {
        cudaFuncSetAttribute(ch_main, cudaFuncAttributeMaxDynamicSharedMemorySize,
                             (int)sizeof(SM));
        attr_set = true;
    }

    ch_init<<<65, 256>>>(gp_lin_w, lin_w);

    float* lossp;
    bool write_mean = true;
    if (out_size >= NB + 1) {
        lossp = out + 1;
    } else if (out_size == NB) {
        lossp = out; write_mean = false;
    } else {
        void* p = nullptr;
        cudaGetSymbolAddress(&p, g_loss_scratch);
        lossp = (float*)p;
    }

    ch_main<<<NB, 256, sizeof(SM)>>>(points, products, lin_b, gp_a, gp_w,
                                     mlp_w1, mlp_b1, mlp_w2, mlp_b2, lossp);
    if (write_mean)
        ch_reduce<<<1, NB>>>(lossp, out);
}

// round 8
// speedup vs baseline: 3.4945x; 1.1106x over previous
#include <cuda_runtime.h>

constexpr int NB = 256;

constexpr int cpopc(int x){int c=0;while(x){c+=x&1;x>>=1;}return c;}

struct Alg {
    int qt[64];
    short kk[64][64];     // k(i,j)
    short sx[64][64];     // widx + 64*sign  (index into signed-W table)
    int   cls[4][20];
    int   ncl[4];
    int   perm[4][16];    // row assignment per jq-group (class-grouped)
};
constexpr Alg build_alg(){
    Alg a{};
    int mask[64]={}, pos[64]={};
    int idx=0;
    for(int g=0;g<=6;++g) for(int m=0;m<64;++m) if(cpopc(m)==g){mask[idx]=m;idx++;}
    for(int i=0;i<64;++i) pos[mask[i]]=i;
    for(int i=0;i<64;++i){
        a.qt[i]=cpopc(mask[i])&3;
        a.cls[a.qt[i]][a.ncl[a.qt[i]]]=i;
        a.ncl[a.qt[i]]++;
    }
    for(int i=0;i<64;++i) for(int j=0;j<64;++j){
        const int mk=mask[i]^mask[j];
        const int k=pos[mk];
        int s=0,t=mask[i]>>1;
        while(t){s+=cpopc(t&mk);t>>=1;}
        a.kk[i][j]=(short)k;
        a.sx[i][j]=(short)(((a.qt[i]*4+a.qt[j])*4+a.qt[k]) + ((s&1)?64:0));
    }
    // class-grouped permutation: ncl = {16,12,16,20}
    for(int q=0;q<16;++q) a.perm[0][q]=a.cls[0][q];           // 16 x c0
    for(int q=0;q<12;++q) a.perm[1][q]=a.cls[1][q];           // 12 x c1
    for(int q=0;q<4; ++q) a.perm[1][12+q]=a.cls[3][q];        //  4 x c3
    for(int q=0;q<16;++q) a.perm[2][q]=a.cls[2][q];           // 16 x c2
    for(int q=0;q<16;++q) a.perm[3][q]=a.cls[3][4+q];         // 16 x c3
    return a;
}
__device__ constexpr Alg ALG = build_alg();

// ---- packed f32x2 helpers --------------------------------------------------
typedef unsigned long long ull;

__device__ __forceinline__ ull pk2(float lo, float hi){
    ull r;
    asm("mov.b64 %0, {%1, %2};" : "=l"(r)
        : "r"(__float_as_uint(lo)), "r"(__float_as_uint(hi)));
    return r;
}
__device__ __forceinline__ ull mul2(ull a, ull b){
    ull r; asm("mul.rn.f32x2 %0, %1, %2;" : "=l"(r) : "l"(a), "l"(b)); return r;
}
__device__ __forceinline__ ull fma2(ull a, ull b, ull c){
    ull r; asm("fma.rn.f32x2 %0, %1, %2, %3;" : "=l"(r) : "l"(a), "l"(b), "l"(c)); return r;
}
__device__ __forceinline__ void upk2(ull v, float& lo, float& hi){
    unsigned x, y;
    asm("mov.b64 {%0, %1}, %2;" : "=r"(x), "=r"(y) : "l"(v));
    lo = __uint_as_float(x); hi = __uint_as_float(y);
}

__device__ float g_lwT[4*4*64*64];   // [l][c][m][f]
__device__ float g_lin1T[1024];      // [m][f]
__device__ float g_loss_scratch[NB];

// Coalesced init: one float4 (c=0..3) per (l,f,m) tuple.
__global__ void ch_init(const float* __restrict__ gp_lin_w,
                        const float* __restrict__ lin_w)
{
    const int t = threadIdx.x;
    if (blockIdx.x < 64) {
        const int s = blockIdx.x*256 + t;          // (l,f,m), m fastest
        const int m = s & 63, f = (s>>6) & 63, l = s>>12;
        const float4 v = reinterpret_cast<const float4*>(gp_lin_w)[s];
        float* dst = g_lwT + l*16384 + m*64 + f;
        dst[0]       = v.x;
        dst[4096]    = v.y;
        dst[8192]    = v.z;
        dst[12288]   = v.w;
    } else {
        #pragma unroll
        for (int r=0;r<4;++r){
            const int e=r*256+t, m=e>>6, f=e&63;
            g_lin1T[e] = lin_w[(f*16+m)*4 + 1];
        }
    }
}

struct SM {
    float A[4096];      // x [i*64+f]
    float Bv[4224];     // xr [i*64+f]; reused for mlp_w1 [f*65+n]
    float W[8320];      // SIGNED gp_w [f*129 + sx], sx in 0..127 (bit6 = neg)
    float F[256];       // factors / partials [c*64+f]
    float y[64], h[64], pts[96];
};

template<int JQ>
__device__ __forceinline__ void sec_lin(const float* __restrict__ Ash,
                                        float* __restrict__ Bvf,
                                        const float* __restrict__ lwf)
{
    ull LW2[32];
    #pragma unroll
    for (int q=0;q<16;++q) {
        constexpr auto P = ALG.perm[JQ];
        const int i = P[q];
        if (q==0 || ALG.qt[P[q]]!=ALG.qt[P[q-1]]) {
            const float* p = lwf + ALG.qt[i]*4096;
            #pragma unroll
            for (int m=0;m<32;++m)
                LW2[m] = pk2(p[(2*m)*64], p[(2*m+1)*64]);
        }
        const ull* Ar = reinterpret_cast<const ull*>(Ash + i*64);
        ull acca = 0ull, accb = 0ull;
        #pragma unroll
        for (int u=0;u<16;++u){
            acca = fma2(LW2[2*u+0], Ar[2*u+0], acca);
            accb = fma2(LW2[2*u+1], Ar[2*u+1], accb);
        }
        float a0,a1,b0,b1;
        upk2(acca, a0, a1);
        upk2(accb, b0, b1);
        Bvf[i*64] = (a0+b0) + (a1+b1);
    }
}

template<int C>
__device__ __forceinline__ void sec_fact(const float* __restrict__ Bvf,
                                         float* __restrict__ Ff,
                                         const float* __restrict__ gp_a,
                                         int l, int f)
{
    float s = 0.f;
    #pragma unroll
    for (int u=0; u<ALG.ncl[C]; ++u) {
        const float v = Bvf[ALG.cls[C][u]*64];
        s = fmaf(v, v, s);
    }
    const float nrm = sqrtf(fmaxf(s, 1e-12f));
    const float av  = gp_a[(l*64+f)*4 + C];
    const float sig = 1.f/(1.f+expf(-av));
    Ff[C*64] = 1.f/(fmaf(sig, nrm-1.f, 1.f) + 1e-6f);
}

template<int JQ>
__device__ __forceinline__ void sec_gp(const float* __restrict__ Af,
                                       const float* __restrict__ Bvf,
                                       const float* __restrict__ Wf,
                                       const float* __restrict__ Ff,
                                       float (&out)[16])
{
    float fc[4];
    #pragma unroll
    for (int c=0;c<4;++c) fc[c] = Ff[c*64];
    float B[64];
    #pragma unroll
    for (int k=0;k<64;++k) B[k] = Bvf[k*64] * fc[ALG.qt[k]];
    ull acc2[8];
    #pragma unroll
    for (int qp=0;qp<8;++qp) acc2[qp] = 0ull;
    #pragma unroll
    for (int i=0;i<64;++i) {
        const float xi = Af[i*64];
        const ull X2 = pk2(xi, xi);
        #pragma unroll
        for (int qp=0;qp<8;++qp) {
            const int j0 = ALG.perm[JQ][2*qp];
            const int j1 = ALG.perm[JQ][2*qp+1];
            const ull b2 = pk2(B[ALG.kk[i][j0]], B[ALG.kk[i][j1]]);
            const ull w2 = pk2(Wf[ALG.sx[i][j0]], Wf[ALG.sx[i][j1]]);
            acc2[qp] = fma2(w2, mul2(X2, b2), acc2[qp]);
        }
    }
    #pragma unroll
    for (int qp=0;qp<8;++qp)
        upk2(acc2[qp], out[2*qp], out[2*qp+1]);
}

template<int JQ>
__device__ __forceinline__ void sec_store(float* __restrict__ Ash, int f,
                                          const float (&acc)[16])
{
    #pragma unroll
    for (int q=0;q<16;++q)
        Ash[ALG.perm[JQ][q]*64 + f] = acc[q];
}

__global__ void __launch_bounds__(256, 2)
ch_main(const float* __restrict__ points,
        const float* __restrict__ products,
        const float* __restrict__ lin_b,
        const float* __restrict__ gp_a,
        const float* __restrict__ gp_w,
        const float* __restrict__ mlp_w1,
        const float* __restrict__ mlp_b1,
        const float* __restrict__ mlp_w2,
        const float* __restrict__ mlp_b2,
        float* __restrict__ lossp)
{
    extern __shared__ unsigned char smraw[];
    SM* s = reinterpret_cast<SM*>(smraw);

    const int t  = threadIdx.x;
    const int b  = blockIdx.x;
    const int f  = t & 63;
    const int jq = t >> 6;

    if (t < 96) s->pts[t] = points[b*96 + t];
    for (int e = 448 + t; e < 4096; e += 256) s->A[e] = 0.f;
    if (t < 64) s->A[t] = lin_b[t];
    __syncthreads();

    for (int d = jq; d < 6; d += 4) {
        float acc = 0.f;
        #pragma unroll
        for (int m=0;m<16;++m)
            acc = fmaf(s->pts[m*6+d], g_lin1T[m*64+f], acc);
        s->A[(1+d)*64 + f] = acc;
    }
    __syncthreads();

    float acc[16];
    for (int l = 0; l < 4; ++l) {
        {   // stage SIGNED gp_w: W[f*129+w] = +v, W[f*129+64+w] = -v
            const float* gw = gp_w + l*4096;
            #pragma unroll
            for (int r=0;r<16;++r) {
                const int e = r*256+t, ff=e>>6, w=e&63;
                const float v = gw[e];
                s->W[ff*129+w]    =  v;
                s->W[ff*129+64+w] = -v;
            }
        }
        switch (jq) {
            case 0:  sec_lin<0>(s->A, s->Bv+f, g_lwT + l*16384 + f); break;
            case 1:  sec_lin<1>(s->A, s->Bv+f, g_lwT + l*16384 + f); break;
            case 2:  sec_lin<2>(s->A, s->Bv+f, g_lwT + l*16384 + f); break;
            default: sec_lin<3>(s->A, s->Bv+f, g_lwT + l*16384 + f); break;
        }
        __syncthreads();
        switch (jq) {
            case 0:  sec_fact<0>(s->Bv+f, s->F+f, gp_a, l, f); break;
            case 1:  sec_fact<1>(s->Bv+f, s->F+f, gp_a, l, f); break;
            case 2:  sec_fact<2>(s->Bv+f, s->F+f, gp_a, l, f); break;
            default: sec_fact<3>(s->Bv+f, s->F+f, gp_a, l, f); break;
        }
        __syncthreads();
        switch (jq) {
            case 0:  sec_gp<0>(s->A+f, s->Bv+f, s->W+f*129, s->F+f, acc); break;
            case 1:  sec_gp<1>(s->A+f, s->Bv+f, s->W+f*129, s->F+f, acc); break;
            case 2:  sec_gp<2>(s->A+f, s->Bv+f, s->W+f*129, s->F+f, acc); break;
            default: sec_gp<3>(s->A+f, s->Bv+f, s->W+f*129, s->F+f, acc); break;
        }
        __syncthreads();
        switch (jq) {
            case 0:  sec_store<0>(s->A, f, acc); break;
            case 1:  sec_store<1>(s->A, f, acc); break;
            case 2:  sec_store<2>(s->A, f, acc); break;
            default: sec_store<3>(s->A, f, acc); break;
        }
        __syncthreads();
    }

    // epilogue: norms, MLP, loss
    {
        float sum = 0.f;
        #pragma unroll
        for (int r=0;r<16;++r) {
            const float v = s->A[(jq*16+r)*64+f];
            sum = fmaf(v, v, sum);
        }
        s->F[jq*64+f] = sum;
    }
    #pragma unroll
    for (int r=0;r<16;++r) {              // stage mlp_w1 -> Bv[f*65+n]
        const int e = r*256+t, n=e>>6, ff=e&63;
        s->Bv[ff*65+n] = mlp_w1[e];
    }
    __syncthreads();
    if (t < 64) s->y[t] = sqrtf(s->F[t] + s->F[64+t] + s->F[128+t] + s->F[192+t]);
    __syncthreads();
    if (t < 64) {
        float a = mlp_b1[t];
        #pragma unroll
        for (int ff=0;ff<64;++ff)
            a = fmaf(s->y[ff], s->Bv[ff*65+t], a);
        const float sig = 1.f/(1.f+expf(-a));
        s->h[t] = a * sig * mlp_w2[t];
    }
    __syncthreads();
    if (t == 0) {
        float p = mlp_b2[0];
        for (int n=0;n<64;++n) p += s->h[n];
        const float d = p - products[b];
        lossp[b] = d*d;
    }
}

__global__ void ch_reduce(const float* __restrict__ lossp, float* __restrict__ out)
{
    __shared__ float sred[NB];
    const int t = threadIdx.x;
    sred[t] = lossp[t];
    __syncthreads();
    for (int sft = NB/2; sft > 0; sft >>= 1) {
        if (t < sft) sred[t] += sred[t+sft];
        __syncthreads();
    }
    if (t == 0) out[0] = sred[0] * (1.0f/(float)NB);
}

extern "C" void kernel_launch(void* const* d_in, const int* in_sizes, int n_in,
                              void* d_out, int out_size)
{
    const float* points   = (const float*)d_in[0];
    const float* products = (const float*)d_in[1];
    const float* lin_w    = (const float*)d_in[2];
    const float* lin_b    = (const float*)d_in[3];
    const float* gp_lin_w = (const float*)d_in[4];
    const float* gp_a     = (const float*)d_in[5];
    const float* gp_w     = (const float*)d_in[6];
    const float* mlp_w1   = (const float*)d_in[7];
    const float* mlp_b1   = (const float*)d_in[8];
    const float* mlp_w2   = (const float*)d_in[9];
    const float* mlp_b2   = (const float*)d_in[10];
    float* out = (float*)d_out;

    static bool attr_set = false;
    if (!attr_set) {
        cudaFuncSetAttribute(ch_main, cudaFuncAttributeMaxDynamicSharedMemorySize,
                             (int)sizeof(SM));
        attr_set = true;
    }

    ch_init<<<65, 256>>>(gp_lin_w, lin_w);

    float* lossp;
    bool write_mean = true;
    if (out_size >= NB + 1) {
        lossp = out + 1;
    } else if (out_size == NB) {
        lossp = out; write_mean = false;
    } else {
        void* p = nullptr;
        cudaGetSymbolAddress(&p, g_loss_scratch);
        lossp = (float*)p;
    }

    ch_main<<<NB, 256, sizeof(SM)>>>(points, products, lin_b, gp_a, gp_w,
                                     mlp_w1, mlp_b1, mlp_w2, mlp_b2, lossp);
    if (write_mean)
        ch_reduce<<<1, NB>>>(lossp, out);
}

// round 9
// speedup vs baseline: 4.6080x; 1.3186x over previous
#include <cuda_runtime.h>

constexpr int NB = 256;

constexpr int cpopc(int x){int c=0;while(x){c+=x&1;x>>=1;}return c;}

struct Alg {
    int qt[64];
    short kk[64][64];     // k(i,j)
    short sg[64][64];     // sign bit (1 = negative)
    int   cls[4][20];
    int   ncl[4];
    int   perm[4][16];    // row assignment per jq-group (class-grouped)
};
constexpr Alg build_alg(){
    Alg a{};
    int mask[64]={}, pos[64]={};
    int idx=0;
    for(int g=0;g<=6;++g) for(int m=0;m<64;++m) if(cpopc(m)==g){mask[idx]=m;idx++;}
    for(int i=0;i<64;++i) pos[mask[i]]=i;
    for(int i=0;i<64;++i){
        a.qt[i]=cpopc(mask[i])&3;
        a.cls[a.qt[i]][a.ncl[a.qt[i]]]=i;
        a.ncl[a.qt[i]]++;
    }
    for(int i=0;i<64;++i) for(int j=0;j<64;++j){
        const int mk=mask[i]^mask[j];
        const int k=pos[mk];
        int s=0,t=mask[i]>>1;
        while(t){s+=cpopc(t&mk);t>>=1;}
        a.kk[i][j]=(short)k;
        a.sg[i][j]=(short)(s&1);
    }
    // class-grouped permutation: ncl = {16,12,16,20}
    for(int q=0;q<16;++q) a.perm[0][q]=a.cls[0][q];           // 16 x c0
    for(int q=0;q<12;++q) a.perm[1][q]=a.cls[1][q];           // 12 x c1
    for(int q=0;q<4; ++q) a.perm[1][12+q]=a.cls[3][q];        //  4 x c3
    for(int q=0;q<16;++q) a.perm[2][q]=a.cls[2][q];           // 16 x c2
    for(int q=0;q<16;++q) a.perm[3][q]=a.cls[3][4+q];         // 16 x c3
    return a;
}
__device__ constexpr Alg ALG = build_alg();

// ---- packed f32x2 helpers (lin phase) --------------------------------------
typedef unsigned long long ull;

__device__ __forceinline__ ull pk2(float lo, float hi){
    ull r;
    asm("mov.b64 %0, {%1, %2};" : "=l"(r)
        : "r"(__float_as_uint(lo)), "r"(__float_as_uint(hi)));
    return r;
}
__device__ __forceinline__ ull fma2(ull a, ull b, ull c){
    ull r; asm("fma.rn.f32x2 %0, %1, %2, %3;" : "=l"(r) : "l"(a), "l"(b), "l"(c)); return r;
}
__device__ __forceinline__ void upk2(ull v, float& lo, float& hi){
    unsigned x, y;
    asm("mov.b64 {%0, %1}, %2;" : "=r"(x), "=r"(y) : "l"(v));
    lo = __uint_as_float(x); hi = __uint_as_float(y);
}

__device__ float g_lwT[4*4*64*64];   // [l][c][m][f]
__device__ float g_lin1T[1024];      // [m][f]
__device__ float g_loss_scratch[NB];

// Coalesced init: one float4 (c=0..3) per (l,f,m) tuple.
__global__ void ch_init(const float* __restrict__ gp_lin_w,
                        const float* __restrict__ lin_w)
{
    const int t = threadIdx.x;
    if (blockIdx.x < 64) {
        const int s = blockIdx.x*256 + t;          // (l,f,m), m fastest
        const int m = s & 63, f = (s>>6) & 63, l = s>>12;
        const float4 v = reinterpret_cast<const float4*>(gp_lin_w)[s];
        float* dst = g_lwT + l*16384 + m*64 + f;
        dst[0]       = v.x;
        dst[4096]    = v.y;
        dst[8192]    = v.z;
        dst[12288]   = v.w;
    } else {
        #pragma unroll
        for (int r=0;r<4;++r){
            const int e=r*256+t, m=e>>6, f=e&63;
            g_lin1T[e] = lin_w[(f*16+m)*4 + 1];
        }
    }
}

struct SM {
    float A[4096];      // x [i*64+f]
    float Bv[4224];     // xr [i*64+f]; reused for mlp_w1 [f*65+n]
    float W[4160];      // gp_w [f*65+widx]
    float F[256];       // factors / partials [c*64+f]
    float y[64], h[64], pts[96];
};

template<int JQ>
__device__ __forceinline__ void sec_lin(const float* __restrict__ Ash,
                                        float* __restrict__ Bvf,
                                        const float* __restrict__ lwf)
{
    ull LW2[32];
    #pragma unroll
    for (int q=0;q<16;++q) {
        constexpr auto P = ALG.perm[JQ];
        const int i = P[q];
        if (q==0 || ALG.qt[P[q]]!=ALG.qt[P[q-1]]) {
            const float* p = lwf + ALG.qt[i]*4096;
            #pragma unroll
            for (int m=0;m<32;++m)
                LW2[m] = pk2(p[(2*m)*64], p[(2*m+1)*64]);
        }
        const ull* Ar = reinterpret_cast<const ull*>(Ash + i*64);
        ull acca = 0ull, accb = 0ull;
        #pragma unroll
        for (int u=0;u<16;++u){
            acca = fma2(LW2[2*u+0], Ar[2*u+0], acca);
            accb = fma2(LW2[2*u+1], Ar[2*u+1], accb);
        }
        float a0,a1,b0,b1;
        upk2(acca, a0, a1);
        upk2(accb, b0, b1);
        Bvf[i*64] = (a0+b0) + (a1+b1);
    }
}

template<int C>
__device__ __forceinline__ void sec_fact(const float* __restrict__ Bvf,
                                         float* __restrict__ Ff,
                                         const float* __restrict__ gp_a,
                                         int l, int f)
{
    float s = 0.f;
    #pragma unroll
    for (int u=0; u<ALG.ncl[C]; ++u) {
        const float v = Bvf[ALG.cls[C][u]*64];
        s = fmaf(v, v, s);
    }
    const float nrm = sqrtf(fmaxf(s, 1e-12f));
    const float av  = gp_a[(l*64+f)*4 + C];
    const float sig = 1.f/(1.f+expf(-av));
    Ff[C*64] = 1.f/(fmaf(sig, nrm-1.f, 1.f) + 1e-6f);
}

// GP: acc[q] += XW[qt_k] * (+-B[k]), XW[ck] = x_i * w[qt_i][CJ][ck]
template<int JQ>
__device__ __forceinline__ void sec_gp(const float* __restrict__ Af,
                                       const float* __restrict__ Bvf,
                                       const float* __restrict__ Wf,
                                       const float* __restrict__ Ff,
                                       float (&acc)[16])
{
    constexpr int CJ0 = (JQ==0) ? 0 : (JQ==1 ? 1 : (JQ==2 ? 2 : 3));
    constexpr int NCJ = (JQ==1) ? 2 : 1;   // group 1 also carries class-3 rows

    float fc[4];
    #pragma unroll
    for (int c=0;c<4;++c) fc[c] = Ff[c*64];
    float B[64];
    #pragma unroll
    for (int k=0;k<64;++k) B[k] = Bvf[k*64] * fc[ALG.qt[k]];

    float Wreg[NCJ*16];
    #pragma unroll
    for (int ci=0;ci<4;++ci)
        #pragma unroll
        for (int ck=0;ck<4;++ck) {
            Wreg[ci*4+ck] = Wf[(ci*4+CJ0)*4+ck];
            if (NCJ==2) Wreg[16+ci*4+ck] = Wf[(ci*4+3)*4+ck];
        }

    #pragma unroll
    for (int q=0;q<16;++q) acc[q]=0.f;

    #pragma unroll
    for (int i=0;i<64;++i) {
        const float xi = Af[i*64];
        constexpr int dummy = 0; (void)dummy;
        const int qti = ALG.qt[i];
        float XW[NCJ*4];
        #pragma unroll
        for (int ck=0;ck<4;++ck) {
            XW[ck] = xi * Wreg[qti*4+ck];
            if (NCJ==2) XW[4+ck] = xi * Wreg[16+qti*4+ck];
        }
        #pragma unroll
        for (int q=0;q<16;++q) {
            const int j  = ALG.perm[JQ][q];
            const int k  = ALG.kk[i][j];
            const int ck = ALG.qt[k];
            const int slot = (JQ==1 && q>=12) ? 1 : 0;
            const float xw = XW[slot*4+ck];
            if (ALG.sg[i][j]) acc[q] = fmaf(xw, -B[k], acc[q]);
            else              acc[q] = fmaf(xw,  B[k], acc[q]);
        }
    }
}

template<int JQ>
__device__ __forceinline__ void sec_store(float* __restrict__ Ash, int f,
                                          const float (&acc)[16])
{
    #pragma unroll
    for (int q=0;q<16;++q)
        Ash[ALG.perm[JQ][q]*64 + f] = acc[q];
}

__global__ void __launch_bounds__(256, 2)
ch_main(const float* __restrict__ points,
        const float* __restrict__ products,
        const float* __restrict__ lin_b,
        const float* __restrict__ gp_a,
        const float* __restrict__ gp_w,
        const float* __restrict__ mlp_w1,
        const float* __restrict__ mlp_b1,
        const float* __restrict__ mlp_w2,
        const float* __restrict__ mlp_b2,
        float* __restrict__ lossp)
{
    extern __shared__ unsigned char smraw[];
    SM* s = reinterpret_cast<SM*>(smraw);

    const int t  = threadIdx.x;
    const int b  = blockIdx.x;
    const int f  = t & 63;
    const int jq = t >> 6;

    if (t < 96) s->pts[t] = points[b*96 + t];
    for (int e = 448 + t; e < 4096; e += 256) s->A[e] = 0.f;
    if (t < 64) s->A[t] = lin_b[t];
    __syncthreads();

    for (int d = jq; d < 6; d += 4) {
        float acc = 0.f;
        #pragma unroll
        for (int m=0;m<16;++m)
            acc = fmaf(s->pts[m*6+d], g_lin1T[m*64+f], acc);
        s->A[(1+d)*64 + f] = acc;
    }
    __syncthreads();

    float acc[16];
    for (int l = 0; l < 4; ++l) {
        {   // stage gp_w: W[f*65+w]
            const float* gw = gp_w + l*4096;
            #pragma unroll
            for (int r=0;r<16;++r) {
                const int e = r*256+t, ff=e>>6, w=e&63;
                s->W[ff*65+w] = gw[e];
            }
        }
        switch (jq) {
            case 0:  sec_lin<0>(s->A, s->Bv+f, g_lwT + l*16384 + f); break;
            case 1:  sec_lin<1>(s->A, s->Bv+f, g_lwT + l*16384 + f); break;
            case 2:  sec_lin<2>(s->A, s->Bv+f, g_lwT + l*16384 + f); break;
            default: sec_lin<3>(s->A, s->Bv+f, g_lwT + l*16384 + f); break;
        }
        __syncthreads();
        switch (jq) {
            case 0:  sec_fact<0>(s->Bv+f, s->F+f, gp_a, l, f); break;
            case 1:  sec_fact<1>(s->Bv+f, s->F+f, gp_a, l, f); break;
            case 2:  sec_fact<2>(s->Bv+f, s->F+f, gp_a, l, f); break;
            default: sec_fact<3>(s->Bv+f, s->F+f, gp_a, l, f); break;
        }
        __syncthreads();
        switch (jq) {
            case 0:  sec_gp<0>(s->A+f, s->Bv+f, s->W+f*65, s->F+f, acc); break;
            case 1:  sec_gp<1>(s->A+f, s->Bv+f, s->W+f*65, s->F+f, acc); break;
            case 2:  sec_gp<2>(s->A+f, s->Bv+f, s->W+f*65, s->F+f, acc); break;
            default: sec_gp<3>(s->A+f, s->Bv+f, s->W+f*65, s->F+f, acc); break;
        }
        __syncthreads();
        switch (jq) {
            case 0:  sec_store<0>(s->A, f, acc); break;
            case 1:  sec_store<1>(s->A, f, acc); break;
            case 2:  sec_store<2>(s->A, f, acc); break;
            default: sec_store<3>(s->A, f, acc); break;
        }
        __syncthreads();
    }

    // epilogue: norms, MLP, loss
    {
        float sum = 0.f;
        #pragma unroll
        for (int r=0;r<16;++r) {
            const float v = s->A[(jq*16+r)*64+f];
            sum = fmaf(v, v, sum);
        }
        s->F[jq*64+f] = sum;
    }
    #pragma unroll
    for (int r=0;r<16;++r) {              // stage mlp_w1 -> Bv[f*65+n]
        const int e = r*256+t, n=e>>6, ff=e&63;
        s->Bv[ff*65+n] = mlp_w1[e];
    }
    __syncthreads();
    if (t < 64) s->y[t] = sqrtf(s->F[t] + s->F[64+t] + s->F[128+t] + s->F[192+t]);
    __syncthreads();
    if (t < 64) {
        float a = mlp_b1[t];
        #pragma unroll
        for (int ff=0;ff<64;++ff)
            a = fmaf(s->y[ff], s->Bv[ff*65+t], a);
        const float sig = 1.f/(1.f+expf(-a));
        s->h[t] = a * sig * mlp_w2[t];
    }
    __syncthreads();
    if (t == 0) {
        float p = mlp_b2[0];
        for (int n=0;n<64;++n) p += s->h[n];
        const float d = p - products[b];
        lossp[b] = d*d;
    }
}

__global__ void ch_reduce(const float* __restrict__ lossp, float* __restrict__ out)
{
    __shared__ float sred[NB];
    const int t = threadIdx.x;
    sred[t] = lossp[t];
    __syncthreads();
    for (int sft = NB/2; sft > 0; sft >>= 1) {
        if (t < sft) sred[t] += sred[t+sft];
        __syncthreads();
    }
    if (t == 0) out[0] = sred[0] * (1.0f/(float)NB);
}

extern "C" void kernel_launch(void* const* d_in, const int* in_sizes, int n_in,
                              void* d_out, int out_size)
{
    const float* points   = (const float*)d_in[0];
    const float* products = (const float*)d_in[1];
    const float* lin_w    = (const float*)d_in[2];
    const float* lin_b    = (const float*)d_in[3];
    const float* gp_lin_w = (const float*)d_in[4];
    const float* gp_a     = (const float*)d_in[5];
    const float* gp_w     = (const float*)d_in[6];
    const float* mlp_w1   = (const float*)d_in[7];
    const float* mlp_b1   = (const float*)d_in[8];
    const float* mlp_w2   = (const float*)d_in[9];
    const float* mlp_b2   = (const float*)d_in[10];
    float* out = (float*)d_out;

    static bool attr_set = false;
    if (!attr_set) {
        cudaFuncSetAttribute(ch_main, cudaFuncAttributeMaxDynamicSharedMemorySize,
                             (int)sizeof(SM));
        attr_set = true;
    }

    ch_init<<<65, 256>>>(gp_lin_w, lin_w);

    float* lossp;
    bool write_mean = true;
    if (out_size >= NB + 1) {
        lossp = out + 1;
    } else if (out_size == NB) {
        lossp = out; write_mean = false;
    } else {
        void* p = nullptr;
        cudaGetSymbolAddress(&p, g_loss_scratch);
        lossp = (float*)p;
    }

    ch_main<<<NB, 256, sizeof(SM)>>>(points, products, lin_b, gp_a, gp_w,
                                     mlp_w1, mlp_b1, mlp_w2, mlp_b2, lossp);
    if (write_mean)
        ch_reduce<<<1, NB>>>(lossp, out);
}